// round 8
// baseline (speedup 1.0000x reference)
#include <cuda_runtime.h>
#include <cuda_bf16.h>
#include <math.h>
#include <stdint.h>

#define Bn 32
#define Sn 2048
#define NCHUNK 16

// ------------------------------ device scratch ------------------------------
__device__ float g_D[Bn * 512];
__device__ float g_scores[Bn * Sn];
__device__ float g_weights[Bn * Sn];
__device__ float g_partial[Bn * NCHUNK * 1024];
__device__ int   g_maskmode;
// W_enc staged as bf16 hi/lo, SW128-swizzled [n][k] tiles.
// 32 pieces (nc 0..1 x kc 0..15), each 64KB = [hi 32KB][lo 32KB]
__device__ __align__(16) unsigned char g_Bt[32 * 65536];
// enc staged as bf16 hi/lo, swizzled smem-image pieces.
// piece p = rowblock*16 + kc (rowblock 0..511): 32KB = [hi 16KB][lo 16KB]
__device__ __align__(16) unsigned char g_At[512 * 16 * 32768ull];

// ------------------------------ helpers -------------------------------------
__device__ __forceinline__ uint32_t smem_u32(const void* p) {
    uint32_t a;
    asm("{ .reg .u64 t; cvta.to.shared.u64 t, %1; cvt.u32.u64 %0, t; }"
        : "=r"(a) : "l"(p));
    return a;
}
__device__ __forceinline__ uint32_t swz(uint32_t off) {
    return off ^ ((off >> 3) & 0x70);
}
__device__ __forceinline__ void ldsm4(uint32_t* r, uint32_t addr) {
    asm volatile("ldmatrix.sync.aligned.m8n8.x4.shared.b16 {%0,%1,%2,%3}, [%4];"
                 : "=r"(r[0]), "=r"(r[1]), "=r"(r[2]), "=r"(r[3]) : "r"(addr));
}
__device__ __forceinline__ void mma_bf16(float* c, const uint32_t* a,
                                         uint32_t b0, uint32_t b1) {
    asm("mma.sync.aligned.m16n8k16.row.col.f32.bf16.bf16.f32 "
        "{%0,%1,%2,%3},{%4,%5,%6,%7},{%8,%9},{%0,%1,%2,%3};"
        : "+f"(c[0]), "+f"(c[1]), "+f"(c[2]), "+f"(c[3])
        : "r"(a[0]), "r"(a[1]), "r"(a[2]), "r"(a[3]), "r"(b0), "r"(b1));
}
__device__ __forceinline__ void cp16(uint32_t dst, const void* src) {
    asm volatile("cp.async.cg.shared.global [%0], [%1], 16;"
                 :: "r"(dst), "l"(src));
}
__device__ __forceinline__ void cp_commit() {
    asm volatile("cp.async.commit_group;" ::: "memory");
}
__device__ __forceinline__ void cp_wait0() {
    asm volatile("cp.async.wait_group 0;" ::: "memory");
}

// ------------------------------ mask detect ---------------------------------
__global__ void k_detect_mask(const unsigned char* __restrict__ m) {
    int t = threadIdx.x;
    int found = 0;
    for (int i = 4 * t + 1; i < Bn * Sn; i += 1024)
        if (m[i]) found = 1;
    found = __syncthreads_or(found);
    if (t == 0) g_maskmode = found;
}

// ------------------------------ k0: decoder att -----------------------------
__global__ void k0_decoder(const float* __restrict__ dec,
                           const float* __restrict__ Wd,
                           const float* __restrict__ bd,
                           const float* __restrict__ be) {
    int b = blockIdx.x, t = threadIdx.x;
    __shared__ float ds[512];
    ds[t]       = dec[b * 512 + t];
    ds[t + 256] = dec[b * 512 + t + 256];
    __syncthreads();
#pragma unroll
    for (int a0 = 0; a0 < 2; a0++) {
        int a = t + a0 * 256;
        float acc = be[a] + bd[a];
#pragma unroll 8
        for (int h = 0; h < 512; h++) acc += ds[h] * Wd[h * 512 + a];
        g_D[b * 512 + a] = acc;
    }
}

// ------------------------------ kW: stage W_enc -----------------------------
__global__ void kW_convert(const float* __restrict__ We) {
    int gid = blockIdx.x * 256 + threadIdx.x;   // 0..524287
    int k = gid >> 9, n = gid & 511;
    float w = We[gid];
    __nv_bfloat16 hi = __float2bfloat16(w);
    float rem = w - __bfloat162float(hi);
    __nv_bfloat16 lo = __float2bfloat16(rem);
    int kc = k >> 6, kl = k & 63, nc = n >> 8, nl = n & 255;
    int piece = nc * 16 + kc;
    uint32_t sw = swz((uint32_t)nl * 128u + (uint32_t)kl * 2u);
    unsigned char* basep = g_Bt + (size_t)piece * 65536;
    *(__nv_bfloat16*)(basep + sw)         = hi;
    *(__nv_bfloat16*)(basep + 32768 + sw) = lo;
}

// ------------------------------ kA: stage enc -------------------------------
// gid maps one float4 (4 k-values of one row). Writes swizzled smem image.
__global__ __launch_bounds__(256)
void kA_convert(const float* __restrict__ enc) {
    int base = blockIdx.x * 256 + threadIdx.x;
#pragma unroll
    for (int i = 0; i < 8; i++) {
        int gid = base + i * 2097152;          // 8192 blocks * 256 threads
        int kq = gid & 15;                     // float4 within 64-k chunk
        int rl = (gid >> 4) & 127;             // row within 128-row block
        int kc = (gid >> 11) & 15;             // k chunk
        int rb = gid >> 15;                    // row block 0..511
        float4 f = ((const float4*)enc)[((size_t)(rb * 128 + rl)) * 256 + kc * 16 + kq];
        __nv_bfloat16 h0 = __float2bfloat16(f.x), h1 = __float2bfloat16(f.y);
        __nv_bfloat16 h2 = __float2bfloat16(f.z), h3 = __float2bfloat16(f.w);
        __nv_bfloat16 l0 = __float2bfloat16(f.x - __bfloat162float(h0));
        __nv_bfloat16 l1 = __float2bfloat16(f.y - __bfloat162float(h1));
        __nv_bfloat16 l2 = __float2bfloat16(f.z - __bfloat162float(h2));
        __nv_bfloat16 l3 = __float2bfloat16(f.w - __bfloat162float(h3));
        __nv_bfloat162 ph0 = __nv_bfloat162(h0, h1), ph1 = __nv_bfloat162(h2, h3);
        __nv_bfloat162 pl0 = __nv_bfloat162(l0, l1), pl1 = __nv_bfloat162(l2, l3);
        unsigned char* basep = g_At + (size_t)(rb * 16 + kc) * 32768;
        uint32_t sw = swz((uint32_t)rl * 128u + (uint32_t)kq * 8u);
        *(uint2*)(basep + sw)         = make_uint2(*(uint32_t*)&ph0, *(uint32_t*)&ph1);
        *(uint2*)(basep + 16384 + sw) = make_uint2(*(uint32_t*)&pl0, *(uint32_t*)&pl1);
    }
}

// ------------------------------ K1: HMMA scores -----------------------------
// Dynamic smem: 2 buffers x (A 32KB + B 64KB) = 192KB
#define SA_OFF 0
#define SB_OFF 32768
#define BUFSTRIDE 98304
#define SM_SMEM (2 * BUFSTRIDE)
#define K1_THREADS 512

__global__ __launch_bounds__(K1_THREADS)
void k1_mma(const float* __restrict__ Wa,
            const float* __restrict__ ba) {
    extern __shared__ char smem[];
    __shared__ float s_sc[128];
    const uint32_t sb = smem_u32(smem);
    const int tid = threadIdx.x;
    const int wid = tid >> 5, lid = tid & 31;
    const int r0 = blockIdx.x * 128;
    const int b  = r0 >> 11;
    const int wm = wid & 3;            // m group: rows wm*32..+32
    const int wn = wid >> 2;           // n group: cols wn*64..+64
    const int r4 = lid >> 2, q = lid & 3;

    const uint32_t aoffb = (uint32_t)(wm * 32 + (lid & 15)) * 128u + ((lid >> 4) * 16u);
    const uint32_t boffb = (uint32_t)(wn * 64 + (lid & 7) + ((lid >> 4) << 3)) * 128u +
                           (((lid >> 3) & 1) * 16u);

    if (tid < 128) s_sc[tid] = 0.f;

    // stage helper (A piece + B piece for (nc, kc) into buffer bufsel)
    auto stage = [&](int nc, int kc, int bufsel) {
        const unsigned char* srcA = g_At + (size_t)(blockIdx.x * 16 + kc) * 32768;
        uint32_t dstA = sb + bufsel * BUFSTRIDE + SA_OFF;
#pragma unroll
        for (int v = 0; v < 4; v++)
            cp16(dstA + (v * K1_THREADS + tid) * 16,
                 srcA + (size_t)(v * K1_THREADS + tid) * 16);
        const unsigned char* srcB = g_Bt + (size_t)(nc * 16 + kc) * 65536;
        uint32_t dstB = sb + bufsel * BUFSTRIDE + SB_OFF;
#pragma unroll
        for (int v = 0; v < 8; v++)
            cp16(dstB + (v * K1_THREADS + tid) * 16,
                 srcB + (size_t)(v * K1_THREADS + tid) * 16);
        cp_commit();
    };

    // initial prologue: stage nc=0, kc=0 into buffer 0
    stage(0, 0, 0);
    cp_wait0();
    __syncthreads();

    for (int nc = 0; nc < 2; nc++) {
        float acc[2][8][4];
#pragma unroll
        for (int mt = 0; mt < 2; mt++)
#pragma unroll
            for (int nt = 0; nt < 8; nt++)
#pragma unroll
                for (int v = 0; v < 4; v++) acc[mt][nt][v] = 0.f;

        if (nc == 1) { cp_wait0(); __syncthreads(); }

        for (int kc = 0; kc < 16; kc++) {
            const int cur = kc & 1;
            const uint32_t aB = sb + cur * BUFSTRIDE + SA_OFF;
            const uint32_t bB = sb + cur * BUFSTRIDE + SB_OFF;

            if (kc < 15) stage(nc, kc + 1, cur ^ 1);   // overlap with MMA below

#pragma unroll
            for (int kk = 0; kk < 4; kk++) {
                uint32_t ah[2][4], al[2][4];
#pragma unroll
                for (int mt = 0; mt < 2; mt++) {
                    uint32_t off = aoffb + (uint32_t)(mt * 16) * 128u + kk * 32u;
                    ldsm4(ah[mt], aB + swz(off));
                    ldsm4(al[mt], aB + 16384 + swz(off));
                }
#pragma unroll
                for (int ntp = 0; ntp < 4; ntp++) {
                    uint32_t off = boffb + (uint32_t)(ntp * 16) * 128u + kk * 32u;
                    uint32_t bh[4], bl[4];
                    ldsm4(bh, bB + swz(off));
                    ldsm4(bl, bB + 32768 + swz(off));
#pragma unroll
                    for (int mt = 0; mt < 2; mt++) {
                        mma_bf16(acc[mt][2 * ntp],     ah[mt], bh[0], bh[1]);
                        mma_bf16(acc[mt][2 * ntp],     al[mt], bh[0], bh[1]);
                        mma_bf16(acc[mt][2 * ntp],     ah[mt], bl[0], bl[1]);
                        mma_bf16(acc[mt][2 * ntp + 1], ah[mt], bh[2], bh[3]);
                        mma_bf16(acc[mt][2 * ntp + 1], al[mt], bh[2], bh[3]);
                        mma_bf16(acc[mt][2 * ntp + 1], ah[mt], bl[2], bl[3]);
                    }
                }
            }

            cp_wait0();
            __syncthreads();
        }

        // overlap: stage nc=1 kc=0 under the epilogue math (into buffer 0;
        // its previous contents, kc=14, were consumed and barrier-protected)
        if (nc == 0) stage(1, 0, 0);

        // epilogue: score += tanh(acc + D[col]) * Wa[col]
#pragma unroll
        for (int mt = 0; mt < 2; mt++) {
            float p0 = 0.f, p1 = 0.f;
#pragma unroll
            for (int nt = 0; nt < 8; nt++) {
                int c0 = nc * 256 + wn * 64 + nt * 8 + q * 2;
                float d0v = g_D[b * 512 + c0], d1v = g_D[b * 512 + c0 + 1];
                float w0 = Wa[c0], w1 = Wa[c0 + 1];
                p0 += tanhf(acc[mt][nt][0] + d0v) * w0 + tanhf(acc[mt][nt][1] + d1v) * w1;
                p1 += tanhf(acc[mt][nt][2] + d0v) * w0 + tanhf(acc[mt][nt][3] + d1v) * w1;
            }
            p0 += __shfl_xor_sync(0xffffffffu, p0, 1);
            p0 += __shfl_xor_sync(0xffffffffu, p0, 2);
            p1 += __shfl_xor_sync(0xffffffffu, p1, 1);
            p1 += __shfl_xor_sync(0xffffffffu, p1, 2);
            if (q == 0) {
                atomicAdd(&s_sc[wm * 32 + mt * 16 + r4], p0);
                atomicAdd(&s_sc[wm * 32 + mt * 16 + r4 + 8], p1);
            }
        }
        __syncthreads();
    }

    if (tid < 128) g_scores[r0 + tid] = s_sc[tid] + ba[0];
}

// ------------------------------ k2a: softmax --------------------------------
__global__ void k2a_softmax(const void* __restrict__ masks) {
    int b = blockIdx.x, t = threadIdx.x;
    __shared__ float sm[2048];
    __shared__ float red[256];
    const float NEG_INF = __int_as_float(0xff800000);
    const int mode = g_maskmode;
    const unsigned int*  m32 = (const unsigned int*)masks;
    const unsigned char* m8  = (const unsigned char*)masks;

    float lmax = NEG_INF;
#pragma unroll
    for (int v = 0; v < 8; v++) {
        int idx = v * 256 + t;
        float sc = g_scores[b * 2048 + idx];
        bool masked = mode ? (m8[b * 2048 + idx] != 0) : (m32[b * 2048 + idx] != 0u);
        if (masked) sc = NEG_INF;
        sm[idx] = sc;
        lmax = fmaxf(lmax, sc);
    }
    red[t] = lmax;
    __syncthreads();
    for (int o = 128; o > 0; o >>= 1) {
        if (t < o) red[t] = fmaxf(red[t], red[t + o]);
        __syncthreads();
    }
    float bmax = red[0];
    __syncthreads();

    float lsum = 0.f;
#pragma unroll
    for (int v = 0; v < 8; v++) {
        int idx = v * 256 + t;
        float e = expf(sm[idx] - bmax);
        sm[idx] = e;
        lsum += e;
    }
    red[t] = lsum;
    __syncthreads();
    for (int o = 128; o > 0; o >>= 1) {
        if (t < o) red[t] += red[t + o];
        __syncthreads();
    }
    float inv = 1.f / red[0];
#pragma unroll
    for (int v = 0; v < 8; v++) {
        int idx = v * 256 + t;
        g_weights[b * 2048 + idx] = sm[idx] * inv;
    }
}

// ------------------------------ k2b: weighted sum ---------------------------
__global__ void k2b_partial(const float* __restrict__ enc) {
    int ch = blockIdx.x, b = blockIdx.y, t = threadIdx.x;
    __shared__ float w[128];
    if (t < 128) w[t] = g_weights[b * 2048 + ch * 128 + t];
    __syncthreads();

    const float4* rowbase =
        reinterpret_cast<const float4*>(enc) + (size_t)(b * 2048 + ch * 128) * 256;
    float4 acc = make_float4(0.f, 0.f, 0.f, 0.f);
    for (int si = 0; si < 128; si++) {
        float wv = w[si];
        if (wv != 0.f) {
            float4 v = rowbase[(size_t)si * 256 + t];
            acc.x += wv * v.x; acc.y += wv * v.y;
            acc.z += wv * v.z; acc.w += wv * v.w;
        }
    }
    reinterpret_cast<float4*>(g_partial)[(b * NCHUNK + ch) * 256 + t] = acc;
}

// ------------------------------ k2c: final GEMV -----------------------------
__global__ void k2c_context(const float* __restrict__ We,
                            const float* __restrict__ be,
                            float* __restrict__ out) {
    int b = blockIdx.x, t = threadIdx.x;
    __shared__ float ctx[1024];
    float4 s = make_float4(0.f, 0.f, 0.f, 0.f);
#pragma unroll
    for (int chn = 0; chn < NCHUNK; chn++) {
        float4 v = reinterpret_cast<const float4*>(g_partial)[(b * NCHUNK + chn) * 256 + t];
        s.x += v.x; s.y += v.y; s.z += v.z; s.w += v.w;
    }
    reinterpret_cast<float4*>(ctx)[t] = s;
    __syncthreads();

    float acc0 = be[t], acc1 = be[t + 256];
#pragma unroll 4
    for (int k = 0; k < 1024; k++) {
        float c = ctx[k];
        const float* wr = We + k * 512;
        acc0 += c * wr[t];
        acc1 += c * wr[t + 256];
    }
    out[b * 512 + t]       = acc0;
    out[b * 512 + t + 256] = acc1;
}

// ---------------------------------------------------------------------------
extern "C" void kernel_launch(void* const* d_in, const int* in_sizes, int n_in,
                              void* d_out, int out_size) {
    const float*         enc   = (const float*)d_in[0];
    const float*         dec   = (const float*)d_in[1];
    const unsigned char* masks = (const unsigned char*)d_in[2];
    const float*         We    = (const float*)d_in[3];
    const float*         be    = (const float*)d_in[4];
    const float*         Wd    = (const float*)d_in[5];
    const float*         bd    = (const float*)d_in[6];
    const float*         Wa    = (const float*)d_in[7];
    const float*         ba    = (const float*)d_in[8];
    float* out = (float*)d_out;

    static int configured = 0;
    if (!configured) {
        cudaFuncSetAttribute(k1_mma, cudaFuncAttributeMaxDynamicSharedMemorySize, SM_SMEM);
        configured = 1;
    }

    k_detect_mask<<<1, 256>>>(masks);
    k0_decoder<<<Bn, 256>>>(dec, Wd, bd, be);
    kW_convert<<<2048, 256>>>(We);
    kA_convert<<<8192, 256>>>(enc);
    k1_mma<<<512, K1_THREADS, SM_SMEM>>>(Wa, ba);
    k2a_softmax<<<Bn, 256>>>((const void*)masks);
    dim3 g2b(NCHUNK, Bn);
    k2b_partial<<<g2b, 256>>>(enc);
    k2c_context<<<Bn, 256>>>(We, be, out);
}

// round 9
// speedup vs baseline: 1.0368x; 1.0368x over previous
#include <cuda_runtime.h>
#include <cuda_bf16.h>
#include <math.h>
#include <stdint.h>

#define Bn 32
#define Sn 2048
#define NCHUNK 16
#define NTILES 512
#define K1_GRID 148

// ------------------------------ device scratch ------------------------------
__device__ float g_D[Bn * 512];
__device__ float g_scores[Bn * Sn];
__device__ float g_weights[Bn * Sn];
__device__ float g_partial[Bn * NCHUNK * 1024];
// W_enc staged as bf16 hi/lo, SW128-swizzled [n][k] tiles.
// 32 pieces (nc 0..1 x kc 0..15), each 64KB = [hi 32KB][lo 32KB]
__device__ __align__(16) unsigned char g_Bt[32 * 65536];
// enc staged as bf16 hi/lo, swizzled smem-image pieces.
// piece p = rowblock*16 + kc (rowblock 0..511): 32KB = [hi 16KB][lo 16KB]
__device__ __align__(16) unsigned char g_At[512 * 16 * 32768ull];

// ------------------------------ helpers -------------------------------------
__device__ __forceinline__ uint32_t smem_u32(const void* p) {
    uint32_t a;
    asm("{ .reg .u64 t; cvta.to.shared.u64 t, %1; cvt.u32.u64 %0, t; }"
        : "=r"(a) : "l"(p));
    return a;
}
__device__ __forceinline__ uint32_t swz(uint32_t off) {
    return off ^ ((off >> 3) & 0x70);
}
__device__ __forceinline__ void ldsm4(uint32_t* r, uint32_t addr) {
    asm volatile("ldmatrix.sync.aligned.m8n8.x4.shared.b16 {%0,%1,%2,%3}, [%4];"
                 : "=r"(r[0]), "=r"(r[1]), "=r"(r[2]), "=r"(r[3]) : "r"(addr));
}
__device__ __forceinline__ void mma_bf16(float* c, const uint32_t* a,
                                         uint32_t b0, uint32_t b1) {
    asm("mma.sync.aligned.m16n8k16.row.col.f32.bf16.bf16.f32 "
        "{%0,%1,%2,%3},{%4,%5,%6,%7},{%8,%9},{%0,%1,%2,%3};"
        : "+f"(c[0]), "+f"(c[1]), "+f"(c[2]), "+f"(c[3])
        : "r"(a[0]), "r"(a[1]), "r"(a[2]), "r"(a[3]), "r"(b0), "r"(b1));
}
__device__ __forceinline__ void cp16(uint32_t dst, const void* src) {
    asm volatile("cp.async.cg.shared.global [%0], [%1], 16;"
                 :: "r"(dst), "l"(src));
}
__device__ __forceinline__ void cp_commit() {
    asm volatile("cp.async.commit_group;" ::: "memory");
}
__device__ __forceinline__ void cp_wait0() {
    asm volatile("cp.async.wait_group 0;" ::: "memory");
}

// ------------------------------ k0: decoder att -----------------------------
__global__ void k0_decoder(const float* __restrict__ dec,
                           const float* __restrict__ Wd,
                           const float* __restrict__ bd,
                           const float* __restrict__ be) {
    int b = blockIdx.x, ah = blockIdx.y, t = threadIdx.x;
    __shared__ float ds[512];
    ds[t]       = dec[b * 512 + t];
    ds[t + 256] = dec[b * 512 + t + 256];
    __syncthreads();
    int a = ah * 256 + t;
    float acc = be[a] + bd[a];
#pragma unroll 8
    for (int h = 0; h < 512; h++) acc += ds[h] * Wd[h * 512 + a];
    g_D[b * 512 + a] = acc;
}

// ------------------------------ kW: stage W_enc -----------------------------
__global__ void kW_convert(const float* __restrict__ We) {
    int gid = blockIdx.x * 256 + threadIdx.x;   // 0..524287
    int k = gid >> 9, n = gid & 511;
    float w = We[gid];
    __nv_bfloat16 hi = __float2bfloat16(w);
    float rem = w - __bfloat162float(hi);
    __nv_bfloat16 lo = __float2bfloat16(rem);
    int kc = k >> 6, kl = k & 63, nc = n >> 8, nl = n & 255;
    int piece = nc * 16 + kc;
    uint32_t sw = swz((uint32_t)nl * 128u + (uint32_t)kl * 2u);
    unsigned char* basep = g_Bt + (size_t)piece * 65536;
    *(__nv_bfloat16*)(basep + sw)         = hi;
    *(__nv_bfloat16*)(basep + 32768 + sw) = lo;
}

// ------------------------------ kA: stage enc -------------------------------
__global__ __launch_bounds__(256)
void kA_convert(const float* __restrict__ enc) {
    int base = blockIdx.x * 256 + threadIdx.x;
#pragma unroll
    for (int i = 0; i < 8; i++) {
        int gid = base + i * 2097152;          // 8192 blocks * 256 threads
        int kq = gid & 15;
        int rl = (gid >> 4) & 127;
        int kc = (gid >> 11) & 15;
        int rb = gid >> 15;
        float4 f = ((const float4*)enc)[((size_t)(rb * 128 + rl)) * 256 + kc * 16 + kq];
        __nv_bfloat16 h0 = __float2bfloat16(f.x), h1 = __float2bfloat16(f.y);
        __nv_bfloat16 h2 = __float2bfloat16(f.z), h3 = __float2bfloat16(f.w);
        __nv_bfloat16 l0 = __float2bfloat16(f.x - __bfloat162float(h0));
        __nv_bfloat16 l1 = __float2bfloat16(f.y - __bfloat162float(h1));
        __nv_bfloat16 l2 = __float2bfloat16(f.z - __bfloat162float(h2));
        __nv_bfloat16 l3 = __float2bfloat16(f.w - __bfloat162float(h3));
        __nv_bfloat162 ph0 = __nv_bfloat162(h0, h1), ph1 = __nv_bfloat162(h2, h3);
        __nv_bfloat162 pl0 = __nv_bfloat162(l0, l1), pl1 = __nv_bfloat162(l2, l3);
        unsigned char* basep = g_At + (size_t)(rb * 16 + kc) * 32768;
        uint32_t sw = swz((uint32_t)rl * 128u + (uint32_t)kq * 8u);
        *(uint2*)(basep + sw)         = make_uint2(*(uint32_t*)&ph0, *(uint32_t*)&ph1);
        *(uint2*)(basep + 16384 + sw) = make_uint2(*(uint32_t*)&pl0, *(uint32_t*)&pl1);
    }
}

// ------------------------------ K1: persistent HMMA scores ------------------
#define SA_OFF 0
#define SB_OFF 32768
#define BUFSTRIDE 98304
#define SM_SMEM (2 * BUFSTRIDE)
#define K1_THREADS 512

__global__ __launch_bounds__(K1_THREADS)
void k1_mma(const float* __restrict__ Wa,
            const float* __restrict__ ba) {
    extern __shared__ char smem[];
    __shared__ float s_sc[128];
    const uint32_t sb = smem_u32(smem);
    const int tid = threadIdx.x;
    const int wid = tid >> 5, lid = tid & 31;
    const int wm = wid & 3;            // m group: rows wm*32..+32
    const int wn = wid >> 2;           // n group: cols wn*64..+64
    const int r4 = lid >> 2, q = lid & 3;

    const uint32_t aoffb = (uint32_t)(wm * 32 + (lid & 15)) * 128u + ((lid >> 4) * 16u);
    const uint32_t boffb = (uint32_t)(wn * 64 + (lid & 7) + ((lid >> 4) << 3)) * 128u +
                           (((lid >> 3) & 1) * 16u);

    const int ntiles = (NTILES - blockIdx.x + K1_GRID - 1) / K1_GRID;
    const int nsteps = ntiles * 32;

    auto stage = [&](int s, int bufsel) {
        int t  = s >> 5;
        int nc = (s >> 4) & 1;
        int kc = s & 15;
        int rb = blockIdx.x + t * K1_GRID;
        const unsigned char* srcA = g_At + (size_t)(rb * 16 + kc) * 32768;
        uint32_t dstA = sb + bufsel * BUFSTRIDE + SA_OFF;
#pragma unroll
        for (int v = 0; v < 4; v++)
            cp16(dstA + (v * K1_THREADS + tid) * 16,
                 srcA + (size_t)(v * K1_THREADS + tid) * 16);
        const unsigned char* srcB = g_Bt + (size_t)(nc * 16 + kc) * 65536;
        uint32_t dstB = sb + bufsel * BUFSTRIDE + SB_OFF;
#pragma unroll
        for (int v = 0; v < 8; v++)
            cp16(dstB + (v * K1_THREADS + tid) * 16,
                 srcB + (size_t)(v * K1_THREADS + tid) * 16);
        cp_commit();
    };

    float acc[2][8][4];
#pragma unroll
    for (int mt = 0; mt < 2; mt++)
#pragma unroll
        for (int nt = 0; nt < 8; nt++)
#pragma unroll
            for (int v = 0; v < 4; v++) acc[mt][nt][v] = 0.f;

    stage(0, 0);
    cp_wait0();
    __syncthreads();

    for (int s = 0; s < nsteps; s++) {
        const int cur = s & 1;
        const int nc = (s >> 4) & 1;
        const int kc = s & 15;
        const int rb = blockIdx.x + (s >> 5) * K1_GRID;
        const uint32_t aB = sb + cur * BUFSTRIDE + SA_OFF;
        const uint32_t bB = sb + cur * BUFSTRIDE + SB_OFF;

        if (s + 1 < nsteps) stage(s + 1, cur ^ 1);   // overlaps MMA below

#pragma unroll
        for (int kk = 0; kk < 4; kk++) {
            uint32_t ah[2][4], al[2][4];
#pragma unroll
            for (int mt = 0; mt < 2; mt++) {
                uint32_t off = aoffb + (uint32_t)(mt * 16) * 128u + kk * 32u;
                ldsm4(ah[mt], aB + swz(off));
                ldsm4(al[mt], aB + 16384 + swz(off));
            }
#pragma unroll
            for (int ntp = 0; ntp < 4; ntp++) {
                uint32_t off = boffb + (uint32_t)(ntp * 16) * 128u + kk * 32u;
                uint32_t bh[4], bl[4];
                ldsm4(bh, bB + swz(off));
                ldsm4(bl, bB + 32768 + swz(off));
#pragma unroll
                for (int mt = 0; mt < 2; mt++) {
                    mma_bf16(acc[mt][2 * ntp],     ah[mt], bh[0], bh[1]);
                    mma_bf16(acc[mt][2 * ntp],     al[mt], bh[0], bh[1]);
                    mma_bf16(acc[mt][2 * ntp],     ah[mt], bl[0], bl[1]);
                    mma_bf16(acc[mt][2 * ntp + 1], ah[mt], bh[2], bh[3]);
                    mma_bf16(acc[mt][2 * ntp + 1], al[mt], bh[2], bh[3]);
                    mma_bf16(acc[mt][2 * ntp + 1], ah[mt], bl[2], bl[3]);
                }
            }
        }

        if (kc == 15) {
            // epilogue for (rb, nc): overlaps in-flight cp.async of step s+1
            const int r0 = rb * 128;
            const int b  = r0 >> 11;
            if (tid < 128) s_sc[tid] = 0.f;
            __syncthreads();
#pragma unroll
            for (int mt = 0; mt < 2; mt++) {
                float p0 = 0.f, p1 = 0.f;
#pragma unroll
                for (int nt = 0; nt < 8; nt++) {
                    int c0 = nc * 256 + wn * 64 + nt * 8 + q * 2;
                    float d0v = g_D[b * 512 + c0], d1v = g_D[b * 512 + c0 + 1];
                    float w0 = Wa[c0], w1 = Wa[c0 + 1];
                    p0 += tanhf(acc[mt][nt][0] + d0v) * w0 + tanhf(acc[mt][nt][1] + d1v) * w1;
                    p1 += tanhf(acc[mt][nt][2] + d0v) * w0 + tanhf(acc[mt][nt][3] + d1v) * w1;
                }
                p0 += __shfl_xor_sync(0xffffffffu, p0, 1);
                p0 += __shfl_xor_sync(0xffffffffu, p0, 2);
                p1 += __shfl_xor_sync(0xffffffffu, p1, 1);
                p1 += __shfl_xor_sync(0xffffffffu, p1, 2);
                if (q == 0) {
                    atomicAdd(&s_sc[wm * 32 + mt * 16 + r4], p0);
                    atomicAdd(&s_sc[wm * 32 + mt * 16 + r4 + 8], p1);
                }
            }
            __syncthreads();
            if (tid < 128) {
                if (nc == 0) g_scores[r0 + tid] = s_sc[tid];
                else         g_scores[r0 + tid] += s_sc[tid] + ba[0];
            }
            // zero accumulators for next (tile, nc)
#pragma unroll
            for (int mt = 0; mt < 2; mt++)
#pragma unroll
                for (int nt = 0; nt < 8; nt++)
#pragma unroll
                    for (int v = 0; v < 4; v++) acc[mt][nt][v] = 0.f;
        }

        cp_wait0();
        __syncthreads();
    }
}

// ------------------------------ k2a: softmax (+mask detect) -----------------
__global__ void k2a_softmax(const unsigned char* __restrict__ masks) {
    int b = blockIdx.x, t = threadIdx.x;
    __shared__ float sm[2048];
    __shared__ float red[256];
    const float NEG_INF = __int_as_float(0xff800000);

    // detect mask element width from first 64KB (safe under both encodings)
    int found = 0;
    for (int j = t; j < 16384; j += 256)
        if (masks[4 * j + 1]) found = 1;
    const int mode = __syncthreads_or(found);   // 1 = byte elems, 0 = 4-byte
    const unsigned int* m32 = (const unsigned int*)masks;

    float lmax = NEG_INF;
#pragma unroll
    for (int v = 0; v < 8; v++) {
        int idx = v * 256 + t;
        float sc = g_scores[b * 2048 + idx];
        bool masked = mode ? (masks[b * 2048 + idx] != 0) : (m32[b * 2048 + idx] != 0u);
        if (masked) sc = NEG_INF;
        sm[idx] = sc;
        lmax = fmaxf(lmax, sc);
    }
    red[t] = lmax;
    __syncthreads();
    for (int o = 128; o > 0; o >>= 1) {
        if (t < o) red[t] = fmaxf(red[t], red[t + o]);
        __syncthreads();
    }
    float bmax = red[0];
    __syncthreads();

    float lsum = 0.f;
#pragma unroll
    for (int v = 0; v < 8; v++) {
        int idx = v * 256 + t;
        float e = expf(sm[idx] - bmax);
        sm[idx] = e;
        lsum += e;
    }
    red[t] = lsum;
    __syncthreads();
    for (int o = 128; o > 0; o >>= 1) {
        if (t < o) red[t] += red[t + o];
        __syncthreads();
    }
    float inv = 1.f / red[0];
#pragma unroll
    for (int v = 0; v < 8; v++) {
        int idx = v * 256 + t;
        g_weights[b * 2048 + idx] = sm[idx] * inv;
    }
}

// ------------------------------ k2b: weighted sum ---------------------------
__global__ void k2b_partial(const float* __restrict__ enc) {
    int ch = blockIdx.x, b = blockIdx.y, t = threadIdx.x;
    __shared__ float w[128];
    if (t < 128) w[t] = g_weights[b * 2048 + ch * 128 + t];
    __syncthreads();

    const float4* rowbase =
        reinterpret_cast<const float4*>(enc) + (size_t)(b * 2048 + ch * 128) * 256;
    float4 acc = make_float4(0.f, 0.f, 0.f, 0.f);
    for (int si = 0; si < 128; si++) {
        float wv = w[si];
        if (wv != 0.f) {
            float4 v = rowbase[(size_t)si * 256 + t];
            acc.x += wv * v.x; acc.y += wv * v.y;
            acc.z += wv * v.z; acc.w += wv * v.w;
        }
    }
    reinterpret_cast<float4*>(g_partial)[(b * NCHUNK + ch) * 256 + t] = acc;
}

// ------------------------------ k2c: final GEMV -----------------------------
__global__ void k2c_context(const float* __restrict__ We,
                            const float* __restrict__ be,
                            float* __restrict__ out) {
    int b = blockIdx.x, t = threadIdx.x;
    __shared__ float ctx[1024];
    float4 s = make_float4(0.f, 0.f, 0.f, 0.f);
#pragma unroll
    for (int chn = 0; chn < NCHUNK; chn++) {
        float4 v = reinterpret_cast<const float4*>(g_partial)[(b * NCHUNK + chn) * 256 + t];
        s.x += v.x; s.y += v.y; s.z += v.z; s.w += v.w;
    }
    reinterpret_cast<float4*>(ctx)[t] = s;
    __syncthreads();

    float acc0 = be[t], acc1 = be[t + 256];
#pragma unroll 4
    for (int k = 0; k < 1024; k++) {
        float c = ctx[k];
        const float* wr = We + k * 512;
        acc0 += c * wr[t];
        acc1 += c * wr[t + 256];
    }
    out[b * 512 + t]       = acc0;
    out[b * 512 + t + 256] = acc1;
}

// ---------------------------------------------------------------------------
extern "C" void kernel_launch(void* const* d_in, const int* in_sizes, int n_in,
                              void* d_out, int out_size) {
    const float*         enc   = (const float*)d_in[0];
    const float*         dec   = (const float*)d_in[1];
    const unsigned char* masks = (const unsigned char*)d_in[2];
    const float*         We    = (const float*)d_in[3];
    const float*         be    = (const float*)d_in[4];
    const float*         Wd    = (const float*)d_in[5];
    const float*         bd    = (const float*)d_in[6];
    const float*         Wa    = (const float*)d_in[7];
    const float*         ba    = (const float*)d_in[8];
    float* out = (float*)d_out;

    static int configured = 0;
    if (!configured) {
        cudaFuncSetAttribute(k1_mma, cudaFuncAttributeMaxDynamicSharedMemorySize, SM_SMEM);
        configured = 1;
    }

    dim3 g0(Bn, 2);
    k0_decoder<<<g0, 256>>>(dec, Wd, bd, be);
    kW_convert<<<2048, 256>>>(We);
    kA_convert<<<8192, 256>>>(enc);
    k1_mma<<<K1_GRID, K1_THREADS, SM_SMEM>>>(Wa, ba);
    k2a_softmax<<<Bn, 256>>>(masks);
    dim3 g2b(NCHUNK, Bn);
    k2b_partial<<<g2b, 256>>>(enc);
    k2c_context<<<Bn, 256>>>(We, be, out);
}